// round 16
// baseline (speedup 1.0000x reference)
#include <cuda_runtime.h>
#include <cuda_fp16.h>
#include <cstdint>

// out[dst[e]] += edge_attr[e] * x[src[e]],  D=64 f32, indices int32.
// History: R2 scatter 58us. R4/R6 bucket+gather 47.6us. R7 fp16 46.8us.
// R10/R15 fused persistent (convert||fill, grid barrier, fp16 gather):
// 45.5us. R8/R9/R12/R13/R14 all showed the sync-load gather is pinned at
// ~24us by L2-latency x scoreboard depth. R16: cp.async (LDGSTS) pipeline --
// x-row copies consume no registers and no scoreboard slots; 2x 4-edge
// batches in flight per warp in smem, wait_group<1> double buffering.

#define BUCKET_CAP 192           // Poisson(40) over 25K bins: max ~85
#define MAX_CB     32768
#define MAX_NODES  131072

__device__ int      g_counts[MAX_CB];                        // zero-init, self-resetting
__device__ int2     g_bucket[(size_t)MAX_CB * BUCKET_CAP];   // {src, attr bits}
__device__ uint2    g_xh[(size_t)MAX_NODES * 16];            // x as fp16: [node] 128B rows
__device__ unsigned g_bar;                                   // monotonic barrier counter

// ---------------- cp.async primitives ----------------
__device__ __forceinline__ void _cpa4(uint32_t dst_smem, const void* src_gmem) {
    asm volatile("cp.async.ca.shared.global [%0], [%1], 4;"
                 :: "r"(dst_smem), "l"(src_gmem));
}
#define CPA_COMMIT() asm volatile("cp.async.commit_group;" ::: "memory")
#define CPA_WAIT1()  asm volatile("cp.async.wait_group 1;" ::: "memory")
#define CPA_WAIT0()  asm volatile("cp.async.wait_group 0;" ::: "memory")

__device__ __forceinline__ uint32_t _smem_u32(const void* p) {
    uint32_t a;
    asm("{ .reg .u64 t; cvta.to.shared.u64 t, %1; cvt.u32.u64 %0, t; }"
        : "=r"(a) : "l"(p));
    return a;
}

// ---------------- helpers ----------------
__device__ __forceinline__ void _fill_one(int s, int d, float w,
                                          int n_coarse, int n_nodes) {
    if ((unsigned)d >= (unsigned)n_coarse) return;
    if ((unsigned)s >= (unsigned)n_nodes) { s = 0; w = 0.f; }
    int pos = atomicAdd(&g_counts[d], 1);
    if (pos < BUCKET_CAP)
        g_bucket[(unsigned)d * BUCKET_CAP + pos] = make_int2(s, __float_as_int(w));
    // overflow: true total stays in g_counts; gather rescans exactly.
}

__device__ __forceinline__ void _acc2(float2& acc, const __half2* __restrict__ xh2,
                                      unsigned s, float wt, unsigned lane) {
    float2 v = __half22float2(xh2[s * 32u + lane]);
    acc.x = fmaf(wt, v.x, acc.x);
    acc.y = fmaf(wt, v.y, acc.y);
}

// Issue one 4-edge batch: 2 uniform int4 meta loads, 4 cp.async row copies.
__device__ __forceinline__ void _issue4(const int2* __restrict__ bp,
                                        uint32_t slot, unsigned lane,
                                        float4* wout) {
    int4 ma = *(const int4*)(bp);        // {s0,w0, s1,w1}
    int4 mb = *(const int4*)(bp + 2);    // {s2,w2, s3,w3}
    const char* xb = (const char*)g_xh;
    unsigned lo = lane * 4u;
    _cpa4(slot +   0 + lo, xb + (unsigned)ma.x * 128u + lo);
    _cpa4(slot + 128 + lo, xb + (unsigned)ma.z * 128u + lo);
    _cpa4(slot + 256 + lo, xb + (unsigned)mb.x * 128u + lo);
    _cpa4(slot + 384 + lo, xb + (unsigned)mb.z * 128u + lo);
    *wout = make_float4(__int_as_float(ma.y), __int_as_float(ma.w),
                        __int_as_float(mb.y), __int_as_float(mb.w));
}

// Consume one 4-edge batch from smem (each lane reads its own 4B).
__device__ __forceinline__ void _consume4(float2& acc, uint32_t slot,
                                          float4 wc, unsigned lane) {
    unsigned lo = lane * 4u;
    #pragma unroll
    for (int e = 0; e < 4; e++) {
        uint32_t u;
        asm volatile("ld.shared.b32 %0, [%1];" : "=r"(u) : "r"(slot + e * 128u + lo));
        __half2 h = *(const __half2*)&u;
        float2 v = __half22float2(h);
        float wt = (e == 0) ? wc.x : (e == 1) ? wc.y : (e == 2) ? wc.z : wc.w;
        acc.x = fmaf(wt, v.x, acc.x);
        acc.y = fmaf(wt, v.y, acc.y);
    }
}

// Replay-safe grid barrier: counter only ever increments; each call's blocks
// wait for the next multiple of gridDim.x. Requires all blocks resident.
__device__ __forceinline__ void _grid_barrier(unsigned nB) {
    __threadfence();
    __syncthreads();
    if (threadIdx.x == 0) {
        unsigned arrive;
        asm volatile("atom.add.release.gpu.u32 %0, [%1], 1;"
                     : "=r"(arrive) : "l"(&g_bar) : "memory");
        arrive += 1;
        unsigned target = ((arrive - 1) / nB + 1) * nB;
        unsigned cur;
        do {
            asm volatile("ld.acquire.gpu.u32 %0, [%1];"
                         : "=r"(cur) : "l"(&g_bar) : "memory");
        } while (cur < target);
    }
    __syncthreads();
}

// ---------------- fused persistent kernel ----------------
__global__ void __launch_bounds__(256, 6)
_fused_kernel(const float4* __restrict__ x4,     // x as [n_nodes*16] float4
              const float2* __restrict__ x2,     // fp32 x (overflow path)
              const int* __restrict__ src, const int* __restrict__ dst,
              const float* __restrict__ attr,
              float2* __restrict__ out2,          // [n_coarse, 32] float2
              int num_edges, int n_coarse, int n_nodes, int vec_ok) {
    __shared__ __align__(16) char sbuf[8][1024];   // 2 slots x 4 edges x 128B per warp

    const unsigned nB  = gridDim.x;
    const unsigned bid = blockIdx.x;
    const unsigned tid = threadIdx.x;

    // ---- phase 1: convert (blocks [0, convB)) || fill (rest) ----
    const unsigned convB = nB / 4;
    if (bid < convB) {
        int n16 = n_nodes * 16;
        for (int t = bid * 256 + tid; t < n16; t += convB * 256) {
            float4 v = x4[t];
            __half2 h0 = __floats2half2_rn(v.x, v.y);
            __half2 h1 = __floats2half2_rn(v.z, v.w);
            uint2 u;
            u.x = *(const unsigned*)&h0;
            u.y = *(const unsigned*)&h1;
            g_xh[t] = u;
        }
    } else {
        const unsigned fB = nB - convB;
        const unsigned fbid = bid - convB;
        int nchunks = (num_edges + 3) / 4;
        for (int ch = fbid * 256 + tid; ch < nchunks; ch += fB * 256) {
            int base = ch * 4;
            if (vec_ok && base + 4 <= num_edges) {
                int4   s4 = *(const int4*)(src + base);
                int4   d4 = *(const int4*)(dst + base);
                float4 w4 = *(const float4*)(attr + base);
                _fill_one(s4.x, d4.x, w4.x, n_coarse, n_nodes);
                _fill_one(s4.y, d4.y, w4.y, n_coarse, n_nodes);
                _fill_one(s4.z, d4.z, w4.z, n_coarse, n_nodes);
                _fill_one(s4.w, d4.w, w4.w, n_coarse, n_nodes);
            } else {
                int m = min(4, num_edges - base);
                for (int k = 0; k < m; k++) {
                    int e = base + k;
                    _fill_one(src[e], dst[e], attr[e], n_coarse, n_nodes);
                }
            }
        }
    }

    // ---- grid barrier: fill + convert complete ----
    _grid_barrier(nB);

    // ---- phase 2: gather, one warp per node, cp.async double-buffered ----
    const __half2* __restrict__ xh2 = (const __half2*)g_xh;
    unsigned lane   = tid & 31;
    unsigned wib    = tid >> 5;                 // warp in block
    uint32_t wbase  = _smem_u32(sbuf[wib]);     // this warp's 1KB buffer
    uint32_t s0 = wbase, s1 = wbase + 512;
    unsigned gwarp  = bid * 8 + wib;
    unsigned nwarps = nB * 8;

    for (int w = gwarp; w < n_coarse; w += nwarps) {
        int raw_cnt = g_counts[w];
        float2 acc = make_float2(0.f, 0.f);

        if (raw_cnt <= BUCKET_CAP) {
            const int2* __restrict__ b = g_bucket + (unsigned)w * BUCKET_CAP;
            int nb4 = raw_cnt >> 2;              // full 4-edge batches
            float4 wA, wB;

            if (nb4 > 0) _issue4(b, s0, lane, &wA);
            CPA_COMMIT();
            if (nb4 > 1) _issue4(b + 4, s1, lane, &wB);
            CPA_COMMIT();

            for (int k = 0; k < nb4; k++) {
                CPA_WAIT1();
                if (k & 1) {
                    _consume4(acc, s1, wB, lane);
                    if (k + 2 < nb4) _issue4(b + (k + 2) * 4, s1, lane, &wB);
                } else {
                    _consume4(acc, s0, wA, lane);
                    if (k + 2 < nb4) _issue4(b + (k + 2) * 4, s0, lane, &wA);
                }
                CPA_COMMIT();
            }
            CPA_WAIT0();    // drain before smem reuse on the next node

            for (int i = nb4 * 4; i < raw_cnt; i++) {
                int2 p = b[i];
                _acc2(acc, xh2, (unsigned)p.x, __int_as_float(p.y), lane);
            }
        } else {
            // overflow (statistically never): exact fp32 rescan
            for (int e = 0; e < num_edges; e++) {
                if (dst[e] == w) {
                    int s = src[e];
                    float wt = attr[e];
                    if ((unsigned)s >= (unsigned)n_nodes) { s = 0; wt = 0.f; }
                    float2 v = x2[(unsigned)s * 32u + lane];
                    acc.x = fmaf(wt, v.x, acc.x);
                    acc.y = fmaf(wt, v.y, acc.y);
                }
            }
        }

        out2[(unsigned)w * 32u + lane] = acc;
        if (lane == 0) g_counts[w] = 0;   // self-reset for next call
    }
}

// ---------- fallback (shapes exceed scratch): atomic scatter, fp32 ----------
__global__ void _zero_out_kernel(float4* __restrict__ out, int n4) {
    int i = blockIdx.x * blockDim.x + threadIdx.x;
    if (i < n4) out[i] = make_float4(0.f, 0.f, 0.f, 0.f);
}

__global__ void __launch_bounds__(256)
_scatter_add_kernel(const float4* __restrict__ x4,
                    const int* __restrict__ src,
                    const int* __restrict__ dst,
                    const float* __restrict__ attr,
                    float* __restrict__ out,
                    int num_edges, int n_nodes, int n_coarse) {
    int t = blockIdx.x * blockDim.x + threadIdx.x;
    int e = t >> 4;
    int c = t & 15;
    if (e >= num_edges) return;
    int s = src[e];
    int d = dst[e];
    float w = attr[e];
    if ((unsigned)s >= (unsigned)n_nodes || (unsigned)d >= (unsigned)n_coarse) return;
    float4 v = x4[(long long)s * 16 + c];
    v.x *= w; v.y *= w; v.z *= w; v.w *= w;
    float* p = out + (long long)d * 64 + c * 4;
    asm volatile("red.global.add.v4.f32 [%0], {%1, %2, %3, %4};"
                 :: "l"(p), "f"(v.x), "f"(v.y), "f"(v.z), "f"(v.w)
                 : "memory");
}

extern "C" void kernel_launch(void* const* d_in, const int* in_sizes, int n_in,
                              void* d_out, int out_size) {
    const float* x    = (const float*)d_in[0];     // [n_nodes, 64] f32
    const int*   eidx = (const int*)d_in[1];       // [2, E] int32
    const float* attr = (const float*)d_in[2];     // [E] f32
    float*       out  = (float*)d_out;             // [n_coarse, 64] f32

    int num_edges = in_sizes[2];
    int n_nodes   = in_sizes[0] / 64;
    int n_coarse  = out_size / 64;
    const int* src = eidx;
    const int* dst = eidx + num_edges;

    if (n_coarse <= MAX_CB && n_nodes <= MAX_NODES) {
        int vec_ok = ((num_edges & 3) == 0) &&
                     ((((unsigned long long)(uintptr_t)eidx) & 15ull) == 0) &&
                     ((((unsigned long long)(uintptr_t)attr) & 15ull) == 0);

        int sms = 148;
        cudaDeviceGetAttribute(&sms, cudaDevAttrMultiProcessorCount, 0);
        int nB = sms * 6;       // launch_bounds(256,6) guarantees residency

        _fused_kernel<<<nB, 256>>>((const float4*)x, (const float2*)x,
                                   src, dst, attr, (float2*)out,
                                   num_edges, n_coarse, n_nodes, vec_ok);
    } else {
        int n4 = out_size / 4;
        _zero_out_kernel<<<(n4 + 255) / 256, 256>>>((float4*)out, n4);
        long long tt = (long long)num_edges * 16;
        _scatter_add_kernel<<<(int)((tt + 255) / 256), 256>>>(
            (const float4*)x, src, dst, attr, out, num_edges, n_nodes, n_coarse);
    }
}

// round 17
// speedup vs baseline: 1.0402x; 1.0402x over previous
#include <cuda_runtime.h>
#include <cuda_fp16.h>
#include <cstdint>

// out[dst[e]] += edge_attr[e] * x[src[e]],  D=64 f32, indices int32.
// History: R2 scatter 58us. R4/R6 bucket+gather 47.6us. R7 fp16 46.8us.
// R10/R15 fused persistent (convert||fill, grid barrier, fp16 gather,
// lb(256,6)): 45.5us. SEVEN gather variants (R8,R9,R11,R12,R13,R14,R16 incl
// cp.async) all regressed/neutral -> gather loop is optimal. R17: phase-1
// only: (a) convB = nB/8 (convert is DRAM-bound ~5us, fill binds -> give
// fill 7/8 of blocks), (b) fill issues its 4 independent atomicAdds
// back-to-back BEFORE the 4 bucket stores, overlapping the ~300cyc atomic
// round trips 4-way instead of serializing them behind stores.

#define BUCKET_CAP 192           // Poisson(40) over 25K bins: max ~85
#define MAX_CB     32768
#define MAX_NODES  131072

__device__ int      g_counts[MAX_CB];                        // zero-init, self-resetting
__device__ int2     g_bucket[(size_t)MAX_CB * BUCKET_CAP];   // {src, attr bits}
__device__ uint2    g_xh[(size_t)MAX_NODES * 16];            // x as fp16: [node][32] half2
__device__ unsigned g_bar;                                   // monotonic barrier counter

// ---------------- helpers ----------------
__device__ __forceinline__ void _fill_one(int s, int d, float w,
                                          int n_coarse, int n_nodes) {
    if ((unsigned)d >= (unsigned)n_coarse) return;
    if ((unsigned)s >= (unsigned)n_nodes) { s = 0; w = 0.f; }
    int pos = atomicAdd(&g_counts[d], 1);
    if (pos < BUCKET_CAP)
        g_bucket[(unsigned)d * BUCKET_CAP + pos] = make_int2(s, __float_as_int(w));
    // overflow: true total stays in g_counts; gather rescans exactly.
}

// 4 edges: all atomics issued before any store -> 4-way atomic MLP.
__device__ __forceinline__ void _fill_four(int4 s4, int4 d4, float4 w4,
                                           int n_coarse, int n_nodes) {
    int   s[4] = {s4.x, s4.y, s4.z, s4.w};
    int   d[4] = {d4.x, d4.y, d4.z, d4.w};
    float w[4] = {w4.x, w4.y, w4.z, w4.w};
    int   pos[4];
    #pragma unroll
    for (int k = 0; k < 4; k++) {
        if ((unsigned)s[k] >= (unsigned)n_nodes) { s[k] = 0; w[k] = 0.f; }
        pos[k] = ((unsigned)d[k] < (unsigned)n_coarse)
                   ? atomicAdd(&g_counts[d[k]], 1)
                   : BUCKET_CAP;                 // marks "skip" for the store
    }
    #pragma unroll
    for (int k = 0; k < 4; k++) {
        if (pos[k] < BUCKET_CAP)
            g_bucket[(unsigned)d[k] * BUCKET_CAP + pos[k]] =
                make_int2(s[k], __float_as_int(w[k]));
    }
}

__device__ __forceinline__ void _acc2(float2& acc, const __half2* __restrict__ xh2,
                                      unsigned s, float wt, unsigned lane) {
    float2 v = __half22float2(xh2[s * 32u + lane]);
    acc.x = fmaf(wt, v.x, acc.x);
    acc.y = fmaf(wt, v.y, acc.y);
}

// Replay-safe grid barrier: counter only ever increments; each call's blocks
// wait for the next multiple of gridDim.x. Requires all blocks resident.
__device__ __forceinline__ void _grid_barrier(unsigned nB) {
    __threadfence();
    __syncthreads();
    if (threadIdx.x == 0) {
        unsigned arrive;
        asm volatile("atom.add.release.gpu.u32 %0, [%1], 1;"
                     : "=r"(arrive) : "l"(&g_bar) : "memory");
        arrive += 1;
        unsigned target = ((arrive - 1) / nB + 1) * nB;
        unsigned cur;
        do {
            asm volatile("ld.acquire.gpu.u32 %0, [%1];"
                         : "=r"(cur) : "l"(&g_bar) : "memory");
        } while (cur < target);
    }
    __syncthreads();
}

// ---------------- fused persistent kernel ----------------
__global__ void __launch_bounds__(256, 6)
_fused_kernel(const float4* __restrict__ x4,     // x as [n_nodes*16] float4
              const float2* __restrict__ x2,     // fp32 x (overflow path)
              const int* __restrict__ src, const int* __restrict__ dst,
              const float* __restrict__ attr,
              float2* __restrict__ out2,          // [n_coarse, 32] float2
              int num_edges, int n_coarse, int n_nodes, int vec_ok) {
    const unsigned nB  = gridDim.x;
    const unsigned bid = blockIdx.x;
    const unsigned tid = threadIdx.x;

    // ---- phase 1: convert (blocks [0, convB)) || fill (rest) ----
    const unsigned convB = (nB / 8 > 0) ? nB / 8 : 1;
    if (bid < convB) {
        int n16 = n_nodes * 16;
        for (int t = bid * 256 + tid; t < n16; t += convB * 256) {
            float4 v = x4[t];
            __half2 h0 = __floats2half2_rn(v.x, v.y);
            __half2 h1 = __floats2half2_rn(v.z, v.w);
            uint2 u;
            u.x = *(const unsigned*)&h0;
            u.y = *(const unsigned*)&h1;
            g_xh[t] = u;
        }
    } else {
        const unsigned fB = nB - convB;
        const unsigned fbid = bid - convB;
        int nchunks = (num_edges + 3) / 4;
        for (int ch = fbid * 256 + tid; ch < nchunks; ch += fB * 256) {
            int base = ch * 4;
            if (vec_ok && base + 4 <= num_edges) {
                int4   s4 = *(const int4*)(src + base);
                int4   d4 = *(const int4*)(dst + base);
                float4 w4 = *(const float4*)(attr + base);
                _fill_four(s4, d4, w4, n_coarse, n_nodes);
            } else {
                int m = min(4, num_edges - base);
                for (int k = 0; k < m; k++) {
                    int e = base + k;
                    _fill_one(src[e], dst[e], attr[e], n_coarse, n_nodes);
                }
            }
        }
    }

    // ---- grid barrier: fill + convert complete ----
    _grid_barrier(nB);

    // ---- phase 2: gather, one warp per node (proven R10/R15 loop) ----
    const __half2* __restrict__ xh2 = (const __half2*)g_xh;
    unsigned lane   = tid & 31;
    unsigned gwarp  = bid * 8 + (tid >> 5);
    unsigned nwarps = nB * 8;

    for (int w = gwarp; w < n_coarse; w += nwarps) {
        int raw_cnt = g_counts[w];
        float2 acc = make_float2(0.f, 0.f);

        if (raw_cnt <= BUCKET_CAP) {
            const int2* __restrict__ b = g_bucket + (unsigned)w * BUCKET_CAP;
            int i = 0;
            for (; i + 4 <= raw_cnt; i += 4) {
                int4 ma = *(const int4*)(b + i);       // {s0,w0, s1,w1}
                int4 mb = *(const int4*)(b + i + 2);   // {s2,w2, s3,w3}
                _acc2(acc, xh2, (unsigned)ma.x, __int_as_float(ma.y), lane);
                _acc2(acc, xh2, (unsigned)ma.z, __int_as_float(ma.w), lane);
                _acc2(acc, xh2, (unsigned)mb.x, __int_as_float(mb.y), lane);
                _acc2(acc, xh2, (unsigned)mb.z, __int_as_float(mb.w), lane);
            }
            for (; i < raw_cnt; i++) {
                int2 p = b[i];
                _acc2(acc, xh2, (unsigned)p.x, __int_as_float(p.y), lane);
            }
        } else {
            // overflow (statistically never): exact fp32 rescan
            for (int e = 0; e < num_edges; e++) {
                if (dst[e] == w) {
                    int s = src[e];
                    float wt = attr[e];
                    if ((unsigned)s >= (unsigned)n_nodes) { s = 0; wt = 0.f; }
                    float2 v = x2[(unsigned)s * 32u + lane];
                    acc.x = fmaf(wt, v.x, acc.x);
                    acc.y = fmaf(wt, v.y, acc.y);
                }
            }
        }

        out2[(unsigned)w * 32u + lane] = acc;
        if (lane == 0) g_counts[w] = 0;   // self-reset for next call
    }
}

// ---------- fallback (shapes exceed scratch): atomic scatter, fp32 ----------
__global__ void _zero_out_kernel(float4* __restrict__ out, int n4) {
    int i = blockIdx.x * blockDim.x + threadIdx.x;
    if (i < n4) out[i] = make_float4(0.f, 0.f, 0.f, 0.f);
}

__global__ void __launch_bounds__(256)
_scatter_add_kernel(const float4* __restrict__ x4,
                    const int* __restrict__ src,
                    const int* __restrict__ dst,
                    const float* __restrict__ attr,
                    float* __restrict__ out,
                    int num_edges, int n_nodes, int n_coarse) {
    int t = blockIdx.x * blockDim.x + threadIdx.x;
    int e = t >> 4;
    int c = t & 15;
    if (e >= num_edges) return;
    int s = src[e];
    int d = dst[e];
    float w = attr[e];
    if ((unsigned)s >= (unsigned)n_nodes || (unsigned)d >= (unsigned)n_coarse) return;
    float4 v = x4[(long long)s * 16 + c];
    v.x *= w; v.y *= w; v.z *= w; v.w *= w;
    float* p = out + (long long)d * 64 + c * 4;
    asm volatile("red.global.add.v4.f32 [%0], {%1, %2, %3, %4};"
                 :: "l"(p), "f"(v.x), "f"(v.y), "f"(v.z), "f"(v.w)
                 : "memory");
}

extern "C" void kernel_launch(void* const* d_in, const int* in_sizes, int n_in,
                              void* d_out, int out_size) {
    const float* x    = (const float*)d_in[0];     // [n_nodes, 64] f32
    const int*   eidx = (const int*)d_in[1];       // [2, E] int32
    const float* attr = (const float*)d_in[2];     // [E] f32
    float*       out  = (float*)d_out;             // [n_coarse, 64] f32

    int num_edges = in_sizes[2];
    int n_nodes   = in_sizes[0] / 64;
    int n_coarse  = out_size / 64;
    const int* src = eidx;
    const int* dst = eidx + num_edges;

    if (n_coarse <= MAX_CB && n_nodes <= MAX_NODES) {
        int vec_ok = ((num_edges & 3) == 0) &&
                     ((((unsigned long long)(uintptr_t)eidx) & 15ull) == 0) &&
                     ((((unsigned long long)(uintptr_t)attr) & 15ull) == 0);

        int sms = 148;
        cudaDeviceGetAttribute(&sms, cudaDevAttrMultiProcessorCount, 0);
        int nB = sms * 6;       // launch_bounds(256,6) guarantees residency

        _fused_kernel<<<nB, 256>>>((const float4*)x, (const float2*)x,
                                   src, dst, attr, (float2*)out,
                                   num_edges, n_coarse, n_nodes, vec_ok);
    } else {
        int n4 = out_size / 4;
        _zero_out_kernel<<<(n4 + 255) / 256, 256>>>((float4*)out, n4);
        long long tt = (long long)num_edges * 16;
        _scatter_add_kernel<<<(int)((tt + 255) / 256), 256>>>(
            (const float4*)x, src, dst, attr, out, num_edges, n_nodes, n_coarse);
    }
}